// round 1
// baseline (speedup 1.0000x reference)
#include <cuda_runtime.h>
#include <cstdint>

#define Np   262144
#define Bn   4
#define Hn   512
#define Wn   512
#define CIN  64
#define COUT 64
#define NINS 16
#define EPSF 1e-5f

// ---------------- device scratch (static, allowed) ----------------
__device__ int   g_idx_map[Bn * Hn * Wn];          // 4 MB
__device__ float g_h[3u * Np * 64u];               // 201 MB raw branch outputs (pre-norm)
__device__ float g_sum [3 * NINS * 64];
__device__ float g_sum2[3 * NINS * 64];
__device__ float g_mean[3 * NINS * 64];
__device__ float g_rinv[3 * NINS * 64];
__device__ int   g_cnt [NINS];
__device__ int   g_ymin[NINS], g_ymax[NINS], g_xmin[NINS], g_xmax[NINS];
__device__ int   g_dil[3 * NINS];

// ---------------- init ----------------
__global__ void k_init() {
    int i = blockIdx.x * blockDim.x + threadIdx.x;
    if (i < Bn * Hn * Wn) g_idx_map[i] = -1;
    if (i < 3 * NINS * 64) { g_sum[i] = 0.f; g_sum2[i] = 0.f; }
    if (i < NINS) {
        g_cnt[i] = 0;
        g_ymin[i] = 0x7FFFFFFF; g_ymax[i] = 0x80000000;
        g_xmin[i] = 0x7FFFFFFF; g_xmax[i] = 0x80000000;
    }
}

// ---------------- scatter idx_map + per-instance bbox/count ----------------
__global__ void k_scatter(const int* __restrict__ idxs, const int* __restrict__ seg) {
    __shared__ int sy0[NINS], sy1[NINS], sx0[NINS], sx1[NINS], sc[NINS];
    int tid = threadIdx.x;
    if (tid < NINS) { sy0[tid] = 0x7FFFFFFF; sy1[tid] = 0x80000000;
                      sx0[tid] = 0x7FFFFFFF; sx1[tid] = 0x80000000; sc[tid] = 0; }
    __syncthreads();
    int i = blockIdx.x * blockDim.x + tid;
    if (i < Np) {
        int b = idxs[3*i], y = idxs[3*i+1], x = idxs[3*i+2];
        g_idx_map[(b * Hn + y) * Wn + x] = i;
        int s = seg[i];
        atomicMin(&sy0[s], y); atomicMax(&sy1[s], y);
        atomicMin(&sx0[s], x); atomicMax(&sx1[s], x);
        atomicAdd(&sc[s], 1);
    }
    __syncthreads();
    if (tid < NINS && sc[tid] > 0) {
        atomicMin(&g_ymin[tid], sy0[tid]); atomicMax(&g_ymax[tid], sy1[tid]);
        atomicMin(&g_xmin[tid], sx0[tid]); atomicMax(&g_xmax[tid], sx1[tid]);
        atomicAdd(&g_cnt[tid], sc[tid]);
    }
}

// ---------------- per-instance dilation ----------------
__global__ void k_dil() {
    int i = threadIdx.x;          // 48 threads
    if (i < 3 * NINS) {
        int s = i & 15, r = i >> 4;
        int rate = (r == 0) ? 1 : (r == 1) ? 3 : 5;
        float hr = (float)(g_ymax[s] - g_ymin[s]) / (float)Hn;
        float wr = (float)(g_xmax[s] - g_xmin[s]) / (float)Wn;
        int d = (int)ceilf(fmaxf(hr, wr) * (float)rate);
        if (d < 1) d = 1;
        g_dil[r * NINS + s] = d;
    }
}

// ---------------- branch conv: h = subm_conv(features, w, b, same_ins=True) ----------------
// 32 points / block, 256 threads: c = tid&63, pq = tid>>6, 8 points per thread.
__global__ void __launch_bounds__(256) k_conv_branch(
    const float* __restrict__ feats, const int* __restrict__ idxs,
    const int* __restrict__ seg, const float* __restrict__ w,
    const float* __restrict__ bias, int br)
{
    __shared__ int   snbr[32 * 9];
    __shared__ float sf[32 * 64];
    __shared__ float sw[64 * 64];

    int tid = threadIdx.x;
    int p0  = blockIdx.x * 32;

    // neighbor indices (with instance mask)
    for (int t = tid; t < 32 * 9; t += 256) {
        int p = t / 9, k = t % 9;
        int gi = p0 + p;
        int b = idxs[3*gi], y = idxs[3*gi+1], x = idxs[3*gi+2];
        int sgi = seg[gi];
        int d = g_dil[br * NINS + sgi];
        int ky = k / 3 - 1, kx = k % 3 - 1;
        int ny = y + ky * d, nx = x + kx * d;
        int nbr = -1;
        if (ny >= 0 && ny < Hn && nx >= 0 && nx < Wn) {
            int n = g_idx_map[(b * Hn + ny) * Wn + nx];
            if (n >= 0 && seg[n] == sgi) nbr = n;
        }
        snbr[t] = nbr;
    }
    __syncthreads();

    int c = tid & 63, pq = tid >> 6;
    float acc[8];
    float bb = bias[c];
#pragma unroll
    for (int j = 0; j < 8; j++) acc[j] = bb;

    for (int k = 0; k < 9; k++) {
        // stage w[k] (64x64)
        const float4* wg  = (const float4*)(w + k * 4096);
        float4*       swv = (float4*)sw;
#pragma unroll
        for (int j = 0; j < 4; j++) swv[tid + 256 * j] = wg[tid + 256 * j];
        // gather masked neighbor features for this tap
#pragma unroll
        for (int j = 0; j < 2; j++) {
            int idx = tid + 256 * j;          // 0..511 float4 slots
            int p = idx >> 4, civ = idx & 15;
            int nbr = snbr[p * 9 + k];
            float4 v = make_float4(0.f, 0.f, 0.f, 0.f);
            if (nbr >= 0) v = ((const float4*)(feats + (size_t)nbr * 64))[civ];
            ((float4*)sf)[p * 16 + civ] = v;
        }
        __syncthreads();
#pragma unroll
        for (int ci = 0; ci < 64; ci += 4) {
            float w0 = sw[(ci + 0) * 64 + c];
            float w1 = sw[(ci + 1) * 64 + c];
            float w2 = sw[(ci + 2) * 64 + c];
            float w3 = sw[(ci + 3) * 64 + c];
#pragma unroll
            for (int j = 0; j < 8; j++) {
                int p = pq + 4 * j;
                float4 f = ((const float4*)sf)[p * 16 + (ci >> 2)];
                acc[j] += f.x * w0 + f.y * w1 + f.z * w2 + f.w * w3;
            }
        }
        __syncthreads();
    }

    float* hout = g_h + (size_t)br * Np * 64;
#pragma unroll
    for (int j = 0; j < 8; j++) {
        int p = pq + 4 * j;
        hout[(size_t)(p0 + p) * 64 + c] = acc[j];
    }
}

// ---------------- segment stats (seg is sorted -> run-length partial sums) ----------------
__global__ void k_stats(const int* __restrict__ seg) {
    int br   = blockIdx.y;
    int base = blockIdx.x * 1024;
    int c  = threadIdx.x & 63;
    int rs = threadIdx.x >> 6;          // 0..3
    const float* h = g_h + (size_t)br * Np * 64;
    float s = 0.f, s2 = 0.f;
    int cur = seg[base + rs];
    for (int j = 0; j < 256; j++) {
        int p = base + rs + 4 * j;
        int sg = seg[p];
        if (sg != cur) {
            atomicAdd(&g_sum [(br * NINS + cur) * 64 + c], s);
            atomicAdd(&g_sum2[(br * NINS + cur) * 64 + c], s2);
            s = 0.f; s2 = 0.f; cur = sg;
        }
        float v = h[(size_t)p * 64 + c];
        s += v; s2 += v * v;
    }
    atomicAdd(&g_sum [(br * NINS + cur) * 64 + c], s);
    atomicAdd(&g_sum2[(br * NINS + cur) * 64 + c], s2);
}

// ---------------- norm tables ----------------
__global__ void k_normfin() {
    int i = blockIdx.x * blockDim.x + threadIdx.x;
    if (i < 3 * NINS * 64) {
        int sgl = (i / 64) % NINS;
        float cnt = (float)g_cnt[sgl];
        float mean = g_sum[i] / cnt;
        float var  = g_sum2[i] / cnt - mean * mean;
        g_mean[i] = mean;
        g_rinv[i] = rsqrtf(var + EPSF);
    }
}

// ---------------- final conv over cat=[features | relu(norm(h1..h3))], d=1, no seg mask ----
__global__ void __launch_bounds__(256) k_conv_final(
    const float* __restrict__ feats, const int* __restrict__ idxs,
    const int* __restrict__ seg, const float* __restrict__ wf,
    const float* __restrict__ bf, float* __restrict__ out)
{
    __shared__ int   snbr [32 * 9];
    __shared__ int   snseg[32 * 9];
    __shared__ float sf[32 * 64];
    __shared__ float sw[64 * 64];

    int tid = threadIdx.x;
    int p0  = blockIdx.x * 32;

    for (int t = tid; t < 32 * 9; t += 256) {
        int p = t / 9, k = t % 9;
        int gi = p0 + p;
        int b = idxs[3*gi], y = idxs[3*gi+1], x = idxs[3*gi+2];
        int ky = k / 3 - 1, kx = k % 3 - 1;
        int ny = y + ky, nx = x + kx;
        int nbr = -1, sgn = 0;
        if (ny >= 0 && ny < Hn && nx >= 0 && nx < Wn) {
            int n = g_idx_map[(b * Hn + ny) * Wn + nx];
            if (n >= 0) { nbr = n; sgn = seg[n]; }
        }
        snbr[t] = nbr; snseg[t] = sgn;
    }
    __syncthreads();

    int c = tid & 63, pq = tid >> 6;
    float acc[8];
    float bb = bf[c];
#pragma unroll
    for (int j = 0; j < 8; j++) acc[j] = bb;

    for (int k = 0; k < 9; k++) {
#pragma unroll
        for (int cic = 0; cic < 4; cic++) {
            // stage weight chunk: wf[k][cic*64 .. cic*64+63][:]
            const float4* wg  = (const float4*)(wf + (size_t)(k * 256 + cic * 64) * 64);
            float4*       swv = (float4*)sw;
#pragma unroll
            for (int j = 0; j < 4; j++) swv[tid + 256 * j] = wg[tid + 256 * j];
            // gather this channel-chunk of cat[nbr]
#pragma unroll
            for (int j = 0; j < 2; j++) {
                int idx = tid + 256 * j;
                int p = idx >> 4, civ = idx & 15;
                int nbr = snbr[p * 9 + k];
                float4 v = make_float4(0.f, 0.f, 0.f, 0.f);
                if (nbr >= 0) {
                    if (cic == 0) {
                        v = ((const float4*)(feats + (size_t)nbr * 64))[civ];
                    } else {
                        int brr = cic - 1;
                        float4 hv = ((const float4*)(g_h + ((size_t)brr * Np + nbr) * 64))[civ];
                        int tb = ((brr * NINS + snseg[p * 9 + k]) << 6) + (civ << 2);
                        float4 m = *(const float4*)(g_mean + tb);
                        float4 r = *(const float4*)(g_rinv + tb);
                        v.x = fmaxf(0.f, (hv.x - m.x) * r.x);
                        v.y = fmaxf(0.f, (hv.y - m.y) * r.y);
                        v.z = fmaxf(0.f, (hv.z - m.z) * r.z);
                        v.w = fmaxf(0.f, (hv.w - m.w) * r.w);
                    }
                }
                ((float4*)sf)[p * 16 + civ] = v;
            }
            __syncthreads();
#pragma unroll
            for (int ci = 0; ci < 64; ci += 4) {
                float w0 = sw[(ci + 0) * 64 + c];
                float w1 = sw[(ci + 1) * 64 + c];
                float w2 = sw[(ci + 2) * 64 + c];
                float w3 = sw[(ci + 3) * 64 + c];
#pragma unroll
                for (int j = 0; j < 8; j++) {
                    int p = pq + 4 * j;
                    float4 f = ((const float4*)sf)[p * 16 + (ci >> 2)];
                    acc[j] += f.x * w0 + f.y * w1 + f.z * w2 + f.w * w3;
                }
            }
            __syncthreads();
        }
    }
#pragma unroll
    for (int j = 0; j < 8; j++) {
        int p = pq + 4 * j;
        out[(size_t)(p0 + p) * 64 + c] = acc[j];
    }
}

// ---------------- launch ----------------
extern "C" void kernel_launch(void* const* d_in, const int* in_sizes, int n_in,
                              void* d_out, int out_size)
{
    const float* feats = (const float*)d_in[0];
    const int*   idxs  = (const int*)  d_in[1];
    const int*   seg   = (const int*)  d_in[2];
    const float* w1    = (const float*)d_in[3];
    const float* b1    = (const float*)d_in[4];
    const float* w2    = (const float*)d_in[5];
    const float* b2    = (const float*)d_in[6];
    const float* w3    = (const float*)d_in[7];
    const float* b3    = (const float*)d_in[8];
    const float* wf    = (const float*)d_in[9];
    const float* bf    = (const float*)d_in[10];
    float* out = (float*)d_out;

    k_init<<<(Bn * Hn * Wn + 255) / 256, 256>>>();
    k_scatter<<<(Np + 255) / 256, 256>>>(idxs, seg);
    k_dil<<<1, 64>>>();

    k_conv_branch<<<Np / 32, 256>>>(feats, idxs, seg, w1, b1, 0);
    k_conv_branch<<<Np / 32, 256>>>(feats, idxs, seg, w2, b2, 1);
    k_conv_branch<<<Np / 32, 256>>>(feats, idxs, seg, w3, b3, 2);

    dim3 sg(Np / 1024, 3);
    k_stats<<<sg, 256>>>(seg);
    k_normfin<<<12, 256>>>();

    k_conv_final<<<Np / 32, 256>>>(feats, idxs, seg, wf, bf, out);
}

// round 3
// speedup vs baseline: 2.7583x; 2.7583x over previous
#include <cuda_runtime.h>
#include <cstdint>

#define Np   262144
#define Bn   4
#define Hn   512
#define Wn   512
#define NINS 16
#define EPSF 1e-5f

// ---------------- device scratch ----------------
__device__ int   g_idx_map[Bn * Hn * Wn];          // 4 MB
__device__ float g_h[3u * Np * 64u];               // raw branch outputs (pre-norm)
__device__ float g_sum [3 * NINS * 64];
__device__ float g_sum2[3 * NINS * 64];
__device__ float g_mean[3 * NINS * 64];
__device__ float g_rinv[3 * NINS * 64];
__device__ int   g_cnt [NINS];
__device__ int   g_ymin[NINS], g_ymax[NINS], g_xmin[NINS], g_xmax[NINS];
__device__ int   g_dil[3 * NINS];

// ---------------- helpers ----------------
__device__ __forceinline__ float tf32r(float x) {
    uint32_t u;
    asm("cvt.rna.tf32.f32 %0, %1;" : "=r"(u) : "f"(x));
    return __uint_as_float(u);
}

__device__ __forceinline__ void mma_tf32(float* d, const float* a, const float* b) {
    uint32_t a0 = __float_as_uint(a[0]), a1 = __float_as_uint(a[1]);
    uint32_t a2 = __float_as_uint(a[2]), a3 = __float_as_uint(a[3]);
    uint32_t b0 = __float_as_uint(b[0]), b1 = __float_as_uint(b[1]);
    asm volatile(
        "mma.sync.aligned.m16n8k8.row.col.f32.tf32.tf32.f32 "
        "{%0,%1,%2,%3}, {%4,%5,%6,%7}, {%8,%9}, {%0,%1,%2,%3};"
        : "+f"(d[0]), "+f"(d[1]), "+f"(d[2]), "+f"(d[3])
        : "r"(a0), "r"(a1), "r"(a2), "r"(a3), "r"(b0), "r"(b1));
}

#define APAD 68
#define SA_ELEMS (128 * APAD)
#define SB_ELEMS (64 * APAD)

// ---------------- init / scatter / dil (proven in round 1) ----------------
__global__ void k_init() {
    int i = blockIdx.x * blockDim.x + threadIdx.x;
    if (i < Bn * Hn * Wn) g_idx_map[i] = -1;
    if (i < 3 * NINS * 64) { g_sum[i] = 0.f; g_sum2[i] = 0.f; }
    if (i < NINS) {
        g_cnt[i] = 0;
        g_ymin[i] = 0x7FFFFFFF; g_ymax[i] = 0x80000000;
        g_xmin[i] = 0x7FFFFFFF; g_xmax[i] = 0x80000000;
    }
}

__global__ void k_scatter(const int* __restrict__ idxs, const int* __restrict__ seg) {
    __shared__ int sy0[NINS], sy1[NINS], sx0[NINS], sx1[NINS], sc[NINS];
    int tid = threadIdx.x;
    if (tid < NINS) { sy0[tid] = 0x7FFFFFFF; sy1[tid] = 0x80000000;
                      sx0[tid] = 0x7FFFFFFF; sx1[tid] = 0x80000000; sc[tid] = 0; }
    __syncthreads();
    int i = blockIdx.x * blockDim.x + tid;
    if (i < Np) {
        int b = idxs[3*i], y = idxs[3*i+1], x = idxs[3*i+2];
        g_idx_map[(b * Hn + y) * Wn + x] = i;
        int s = seg[i];
        atomicMin(&sy0[s], y); atomicMax(&sy1[s], y);
        atomicMin(&sx0[s], x); atomicMax(&sx1[s], x);
        atomicAdd(&sc[s], 1);
    }
    __syncthreads();
    if (tid < NINS && sc[tid] > 0) {
        atomicMin(&g_ymin[tid], sy0[tid]); atomicMax(&g_ymax[tid], sy1[tid]);
        atomicMin(&g_xmin[tid], sx0[tid]); atomicMax(&g_xmax[tid], sx1[tid]);
        atomicAdd(&g_cnt[tid], sc[tid]);
    }
}

__global__ void k_dil() {
    int i = threadIdx.x;
    if (i < 3 * NINS) {
        int s = i & 15, r = i >> 4;
        int rate = (r == 0) ? 1 : (r == 1) ? 3 : 5;
        float hr = (float)(g_ymax[s] - g_ymin[s]) / (float)Hn;
        float wr = (float)(g_xmax[s] - g_xmin[s]) / (float)Wn;
        int d = (int)ceilf(fmaxf(hr, wr) * (float)rate);
        if (d < 1) d = 1;
        g_dil[r * NINS + s] = d;
    }
}

// ---------------- branch conv via mma.sync tf32 ----------------
// block: 128 points x 64 cout. 8 warps as 4(M) x 2(N); warp tile 32x32.
__global__ void __launch_bounds__(256) k_branch_mma(
    const float* __restrict__ feats, const int* __restrict__ idxs,
    const int* __restrict__ seg,
    const float* __restrict__ w1, const float* __restrict__ bias1,
    const float* __restrict__ w2, const float* __restrict__ bias2,
    const float* __restrict__ w3, const float* __restrict__ bias3)
{
    extern __shared__ float sm[];
    float* sA = sm;                         // [128][68]
    float* sB = sm + SA_ELEMS;              // [64][68]   (cout-major, cin inner)
    int*   snbr = (int*)(sm + SA_ELEMS + SB_ELEMS);  // 128*9

    int tid = threadIdx.x;
    int br  = blockIdx.y;
    int p0  = blockIdx.x * 128;
    const float* w    = (br == 0) ? w1 : (br == 1) ? w2 : w3;
    const float* bias = (br == 0) ? bias1 : (br == 1) ? bias2 : bias3;

    // neighbor table
    for (int t = tid; t < 128 * 9; t += 256) {
        int p = t / 9, k = t % 9;
        int gi = p0 + p;
        int b = idxs[3*gi], y = idxs[3*gi+1], x = idxs[3*gi+2];
        int sgi = seg[gi];
        int d = g_dil[br * NINS + sgi];
        int ky = k / 3 - 1, kx = k % 3 - 1;
        int ny = y + ky * d, nx = x + kx * d;
        int nbr = -1;
        if (ny >= 0 && ny < Hn && nx >= 0 && nx < Wn) {
            int n = g_idx_map[(b * Hn + ny) * Wn + nx];
            if (n >= 0 && seg[n] == sgi) nbr = n;
        }
        snbr[t] = nbr;
    }
    __syncthreads();

    int lane = tid & 31, wid = tid >> 5;
    int wm = wid >> 1, wn = wid & 1;
    int gid = lane >> 2, tig = lane & 3;
    int frow = tid >> 1, fhalf = tid & 1;       // A fill: 2 threads per row
    int fci = tid >> 2, fq = tid & 3;           // B fill

    float acc[2][4][4];
#pragma unroll
    for (int mi = 0; mi < 2; mi++)
#pragma unroll
        for (int ni = 0; ni < 4; ni++)
#pragma unroll
            for (int e = 0; e < 4; e++) acc[mi][ni][e] = 0.f;

    for (int k = 0; k < 9; k++) {
        // ---- A fill: gather 32 floats per thread ----
        {
            int nbr = snbr[frow * 9 + k];
            const float4* src = (const float4*)(feats + (size_t)(nbr < 0 ? 0 : nbr) * 64) + fhalf * 8;
            float* dstp = sA + frow * APAD + fhalf * 32;
#pragma unroll
            for (int i = 0; i < 8; i++) {
                float4 f = make_float4(0.f, 0.f, 0.f, 0.f);
                if (nbr >= 0) f = src[i];
                f.x = tf32r(f.x); f.y = tf32r(f.y);
                f.z = tf32r(f.z); f.w = tf32r(f.w);
                *(float4*)(dstp + i * 4) = f;
            }
        }
        // ---- B fill: transpose w[k] (cin x cout) -> sB[cout][cin] ----
        {
            const float* wk = w + k * 4096 + fci * 64;
#pragma unroll
            for (int j = 0; j < 4; j++) {
                int n0 = fq * 16 + j * 4;
                float4 f = *(const float4*)(wk + n0);
                sB[(n0 + 0) * APAD + fci] = tf32r(f.x);
                sB[(n0 + 1) * APAD + fci] = tf32r(f.y);
                sB[(n0 + 2) * APAD + fci] = tf32r(f.z);
                sB[(n0 + 3) * APAD + fci] = tf32r(f.w);
            }
        }
        __syncthreads();

#pragma unroll
        for (int s = 0; s < 8; s++) {
            float a[2][4], b[4][2];
#pragma unroll
            for (int mi = 0; mi < 2; mi++) {
                const float* ap = sA + (wm * 32 + mi * 16 + gid) * APAD + s * 8 + tig;
                a[mi][0] = ap[0];
                a[mi][1] = ap[8 * APAD];
                a[mi][2] = ap[4];
                a[mi][3] = ap[8 * APAD + 4];
            }
#pragma unroll
            for (int ni = 0; ni < 4; ni++) {
                const float* bp = sB + (wn * 32 + ni * 8 + gid) * APAD + s * 8 + tig;
                b[ni][0] = bp[0];
                b[ni][1] = bp[4];
            }
#pragma unroll
            for (int mi = 0; mi < 2; mi++)
#pragma unroll
                for (int ni = 0; ni < 4; ni++)
                    mma_tf32(acc[mi][ni], a[mi], b[ni]);
        }
        __syncthreads();
    }

    // epilogue: + bias, write g_h
    float* hout = g_h + (size_t)br * Np * 64;
#pragma unroll
    for (int ni = 0; ni < 4; ni++) {
        int col = wn * 32 + ni * 8 + tig * 2;
        float2 bb = *(const float2*)(bias + col);
#pragma unroll
        for (int mi = 0; mi < 2; mi++) {
            int row = p0 + wm * 32 + mi * 16 + gid;
            float2 v0 = make_float2(acc[mi][ni][0] + bb.x, acc[mi][ni][1] + bb.y);
            float2 v1 = make_float2(acc[mi][ni][2] + bb.x, acc[mi][ni][3] + bb.y);
            *(float2*)(hout + (size_t)row * 64 + col) = v0;
            *(float2*)(hout + (size_t)(row + 8) * 64 + col) = v1;
        }
    }
}

// ---------------- segment stats (proven) ----------------
__global__ void k_stats(const int* __restrict__ seg) {
    int br   = blockIdx.y;
    int base = blockIdx.x * 1024;
    int c  = threadIdx.x & 63;
    int rs = threadIdx.x >> 6;
    const float* h = g_h + (size_t)br * Np * 64;
    float s = 0.f, s2 = 0.f;
    int cur = seg[base + rs];
    for (int j = 0; j < 256; j++) {
        int p = base + rs + 4 * j;
        int sg = seg[p];
        if (sg != cur) {
            atomicAdd(&g_sum [(br * NINS + cur) * 64 + c], s);
            atomicAdd(&g_sum2[(br * NINS + cur) * 64 + c], s2);
            s = 0.f; s2 = 0.f; cur = sg;
        }
        float v = h[(size_t)p * 64 + c];
        s += v; s2 += v * v;
    }
    atomicAdd(&g_sum [(br * NINS + cur) * 64 + c], s);
    atomicAdd(&g_sum2[(br * NINS + cur) * 64 + c], s2);
}

__global__ void k_normfin() {
    int i = blockIdx.x * blockDim.x + threadIdx.x;
    if (i < 3 * NINS * 64) {
        int sgl = (i / 64) % NINS;
        float cnt = (float)g_cnt[sgl];
        float mean = g_sum[i] / cnt;
        float var  = g_sum2[i] / cnt - mean * mean;
        g_mean[i] = mean;
        g_rinv[i] = rsqrtf(var + EPSF);
    }
}

// ---------------- final conv via mma.sync tf32 ----------------
// 36 stages (tap k x chunk c), accumulate into registers.
__global__ void __launch_bounds__(256) k_final_mma(
    const float* __restrict__ feats, const int* __restrict__ idxs,
    const int* __restrict__ seg, const float* __restrict__ wf,
    const float* __restrict__ bf, float* __restrict__ out)
{
    extern __shared__ float sm[];
    float* sA = sm;
    float* sB = sm + SA_ELEMS;
    int*   snbr  = (int*)(sm + SA_ELEMS + SB_ELEMS);
    int*   snseg = snbr + 128 * 9;

    int tid = threadIdx.x;
    int p0  = blockIdx.x * 128;

    for (int t = tid; t < 128 * 9; t += 256) {
        int p = t / 9, k = t % 9;
        int gi = p0 + p;
        int b = idxs[3*gi], y = idxs[3*gi+1], x = idxs[3*gi+2];
        int ky = k / 3 - 1, kx = k % 3 - 1;
        int ny = y + ky, nx = x + kx;
        int nbr = -1, sgn = 0;
        if (ny >= 0 && ny < Hn && nx >= 0 && nx < Wn) {
            int n = g_idx_map[(b * Hn + ny) * Wn + nx];
            if (n >= 0) { nbr = n; sgn = seg[n]; }
        }
        snbr[t] = nbr; snseg[t] = sgn;
    }
    __syncthreads();

    int lane = tid & 31, wid = tid >> 5;
    int wm = wid >> 1, wn = wid & 1;
    int gid = lane >> 2, tig = lane & 3;
    int frow = tid >> 1, fhalf = tid & 1;
    int fci = tid >> 2, fq = tid & 3;

    float acc[2][4][4];
#pragma unroll
    for (int mi = 0; mi < 2; mi++)
#pragma unroll
        for (int ni = 0; ni < 4; ni++)
#pragma unroll
            for (int e = 0; e < 4; e++) acc[mi][ni][e] = 0.f;

    for (int u = 0; u < 36; u++) {
        int k = u >> 2, c = u & 3;

        // ---- A fill ----
        {
            int nbr = snbr[frow * 9 + k];
            float* dstp = sA + frow * APAD + fhalf * 32;
            if (c == 0) {
                const float4* src = (const float4*)(feats + (size_t)(nbr < 0 ? 0 : nbr) * 64) + fhalf * 8;
#pragma unroll
                for (int i = 0; i < 8; i++) {
                    float4 f = make_float4(0.f, 0.f, 0.f, 0.f);
                    if (nbr >= 0) f = src[i];
                    f.x = tf32r(f.x); f.y = tf32r(f.y);
                    f.z = tf32r(f.z); f.w = tf32r(f.w);
                    *(float4*)(dstp + i * 4) = f;
                }
            } else {
                int brr = c - 1;
                int sgn = snseg[frow * 9 + k];
                int tb  = ((brr * NINS + sgn) << 6) + fhalf * 32;
                const float4* src = (const float4*)(g_h + ((size_t)brr * Np + (size_t)(nbr < 0 ? 0 : nbr)) * 64) + fhalf * 8;
                const float4* m4  = (const float4*)(g_mean + tb);
                const float4* r4  = (const float4*)(g_rinv + tb);
#pragma unroll
                for (int i = 0; i < 8; i++) {
                    float4 v = make_float4(0.f, 0.f, 0.f, 0.f);
                    if (nbr >= 0) {
                        float4 hv = src[i];
                        float4 mm = m4[i];
                        float4 rr = r4[i];
                        v.x = fmaxf(0.f, (hv.x - mm.x) * rr.x);
                        v.y = fmaxf(0.f, (hv.y - mm.y) * rr.y);
                        v.z = fmaxf(0.f, (hv.z - mm.z) * rr.z);
                        v.w = fmaxf(0.f, (hv.w - mm.w) * rr.w);
                    }
                    v.x = tf32r(v.x); v.y = tf32r(v.y);
                    v.z = tf32r(v.z); v.w = tf32r(v.w);
                    *(float4*)(dstp + i * 4) = v;
                }
            }
        }
        // ---- B fill: wf[k][c*64 + ci][n] -> sB[n][ci] ----
        {
            const float* wk = wf + ((size_t)k * 256 + c * 64 + fci) * 64;
#pragma unroll
            for (int j = 0; j < 4; j++) {
                int n0 = fq * 16 + j * 4;
                float4 f = *(const float4*)(wk + n0);
                sB[(n0 + 0) * APAD + fci] = tf32r(f.x);
                sB[(n0 + 1) * APAD + fci] = tf32r(f.y);
                sB[(n0 + 2) * APAD + fci] = tf32r(f.z);
                sB[(n0 + 3) * APAD + fci] = tf32r(f.w);
            }
        }
        __syncthreads();

#pragma unroll
        for (int s = 0; s < 8; s++) {
            float a[2][4], b[4][2];
#pragma unroll
            for (int mi = 0; mi < 2; mi++) {
                const float* ap = sA + (wm * 32 + mi * 16 + gid) * APAD + s * 8 + tig;
                a[mi][0] = ap[0];
                a[mi][1] = ap[8 * APAD];
                a[mi][2] = ap[4];
                a[mi][3] = ap[8 * APAD + 4];
            }
#pragma unroll
            for (int ni = 0; ni < 4; ni++) {
                const float* bp = sB + (wn * 32 + ni * 8 + gid) * APAD + s * 8 + tig;
                b[ni][0] = bp[0];
                b[ni][1] = bp[4];
            }
#pragma unroll
            for (int mi = 0; mi < 2; mi++)
#pragma unroll
                for (int ni = 0; ni < 4; ni++)
                    mma_tf32(acc[mi][ni], a[mi], b[ni]);
        }
        __syncthreads();
    }

#pragma unroll
    for (int ni = 0; ni < 4; ni++) {
        int col = wn * 32 + ni * 8 + tig * 2;
        float2 bb = *(const float2*)(bf + col);
#pragma unroll
        for (int mi = 0; mi < 2; mi++) {
            int row = p0 + wm * 32 + mi * 16 + gid;
            float2 v0 = make_float2(acc[mi][ni][0] + bb.x, acc[mi][ni][1] + bb.y);
            float2 v1 = make_float2(acc[mi][ni][2] + bb.x, acc[mi][ni][3] + bb.y);
            *(float2*)(out + (size_t)row * 64 + col) = v0;
            *(float2*)(out + (size_t)(row + 8) * 64 + col) = v1;
        }
    }
}

// ---------------- launch ----------------
#define SMEM_BRANCH ((SA_ELEMS + SB_ELEMS + 128 * 9) * 4)
#define SMEM_FINAL  ((SA_ELEMS + SB_ELEMS + 2 * 128 * 9) * 4)

extern "C" void kernel_launch(void* const* d_in, const int* in_sizes, int n_in,
                              void* d_out, int out_size)
{
    const float* feats = (const float*)d_in[0];
    const int*   idxs  = (const int*)  d_in[1];
    const int*   seg   = (const int*)  d_in[2];
    const float* w1    = (const float*)d_in[3];
    const float* b1    = (const float*)d_in[4];
    const float* w2    = (const float*)d_in[5];
    const float* b2    = (const float*)d_in[6];
    const float* w3    = (const float*)d_in[7];
    const float* b3    = (const float*)d_in[8];
    const float* wf    = (const float*)d_in[9];
    const float* bf    = (const float*)d_in[10];
    float* out = (float*)d_out;

    cudaFuncSetAttribute(k_branch_mma, cudaFuncAttributeMaxDynamicSharedMemorySize, SMEM_BRANCH);
    cudaFuncSetAttribute(k_final_mma,  cudaFuncAttributeMaxDynamicSharedMemorySize, SMEM_FINAL);

    k_init<<<(Bn * Hn * Wn + 255) / 256, 256>>>();
    k_scatter<<<(Np + 255) / 256, 256>>>(idxs, seg);
    k_dil<<<1, 64>>>();

    dim3 gb(Np / 128, 3);
    k_branch_mma<<<gb, 256, SMEM_BRANCH>>>(feats, idxs, seg, w1, b1, w2, b2, w3, b3);

    dim3 sg(Np / 1024, 3);
    k_stats<<<sg, 256>>>(seg);
    k_normfin<<<12, 256>>>();

    k_final_mma<<<Np / 128, 256, SMEM_FINAL>>>(feats, idxs, seg, wf, bf, out);
}

// round 4
// speedup vs baseline: 3.1971x; 1.1591x over previous
#include <cuda_runtime.h>
#include <cstdint>

#define Np   262144
#define Bn   4
#define Hn   512
#define Wn   512
#define NINS 16
#define EPSF 1e-5f

// ---------------- device scratch ----------------
__device__ int   g_idx_map[Bn * Hn * Wn];          // 4 MB
__device__ float g_h[3u * Np * 64u];               // raw branch outputs (pre-norm)
__device__ float g_sum [3 * NINS * 64];
__device__ float g_sum2[3 * NINS * 64];
__device__ float g_mean[3 * NINS * 64];
__device__ float g_rinv[3 * NINS * 64];
__device__ int   g_cnt [NINS];
__device__ int   g_ymin[NINS], g_ymax[NINS], g_xmin[NINS], g_xmax[NINS];
__device__ int   g_dil[3 * NINS];

// ---------------- helpers ----------------
__device__ __forceinline__ float tf32r(float x) {
    uint32_t u;
    asm("cvt.rna.tf32.f32 %0, %1;" : "=r"(u) : "f"(x));
    return __uint_as_float(u);
}

__device__ __forceinline__ void mma_tf32(float* d, const float* a, const float* b) {
    uint32_t a0 = __float_as_uint(a[0]), a1 = __float_as_uint(a[1]);
    uint32_t a2 = __float_as_uint(a[2]), a3 = __float_as_uint(a[3]);
    uint32_t b0 = __float_as_uint(b[0]), b1 = __float_as_uint(b[1]);
    asm volatile(
        "mma.sync.aligned.m16n8k8.row.col.f32.tf32.tf32.f32 "
        "{%0,%1,%2,%3}, {%4,%5,%6,%7}, {%8,%9}, {%0,%1,%2,%3};"
        : "+f"(d[0]), "+f"(d[1]), "+f"(d[2]), "+f"(d[3])
        : "r"(a0), "r"(a1), "r"(a2), "r"(a3), "r"(b0), "r"(b1));
}

#define APAD 68
#define SA_ELEMS (128 * APAD)
#define SB_ELEMS (64 * APAD)

// ---------------- init / scatter / dil (proven) ----------------
__global__ void k_init() {
    int i = blockIdx.x * blockDim.x + threadIdx.x;
    if (i < Bn * Hn * Wn) g_idx_map[i] = -1;
    if (i < 3 * NINS * 64) { g_sum[i] = 0.f; g_sum2[i] = 0.f; }
    if (i < NINS) {
        g_cnt[i] = 0;
        g_ymin[i] = 0x7FFFFFFF; g_ymax[i] = 0x80000000;
        g_xmin[i] = 0x7FFFFFFF; g_xmax[i] = 0x80000000;
    }
}

__global__ void k_scatter(const int* __restrict__ idxs, const int* __restrict__ seg) {
    __shared__ int sy0[NINS], sy1[NINS], sx0[NINS], sx1[NINS], sc[NINS];
    int tid = threadIdx.x;
    if (tid < NINS) { sy0[tid] = 0x7FFFFFFF; sy1[tid] = 0x80000000;
                      sx0[tid] = 0x7FFFFFFF; sx1[tid] = 0x80000000; sc[tid] = 0; }
    __syncthreads();
    int i = blockIdx.x * blockDim.x + tid;
    if (i < Np) {
        int b = idxs[3*i], y = idxs[3*i+1], x = idxs[3*i+2];
        g_idx_map[(b * Hn + y) * Wn + x] = i;
        int s = seg[i];
        atomicMin(&sy0[s], y); atomicMax(&sy1[s], y);
        atomicMin(&sx0[s], x); atomicMax(&sx1[s], x);
        atomicAdd(&sc[s], 1);
    }
    __syncthreads();
    if (tid < NINS && sc[tid] > 0) {
        atomicMin(&g_ymin[tid], sy0[tid]); atomicMax(&g_ymax[tid], sy1[tid]);
        atomicMin(&g_xmin[tid], sx0[tid]); atomicMax(&g_xmax[tid], sx1[tid]);
        atomicAdd(&g_cnt[tid], sc[tid]);
    }
}

__global__ void k_dil() {
    int i = threadIdx.x;
    if (i < 3 * NINS) {
        int s = i & 15, r = i >> 4;
        int rate = (r == 0) ? 1 : (r == 1) ? 3 : 5;
        float hr = (float)(g_ymax[s] - g_ymin[s]) / (float)Hn;
        float wr = (float)(g_xmax[s] - g_xmin[s]) / (float)Wn;
        int d = (int)ceilf(fmaxf(hr, wr) * (float)rate);
        if (d < 1) d = 1;
        g_dil[r * NINS + s] = d;
    }
}

// ---------------- branch conv via mma.sync tf32, coalesced gather ----------
// block: 128 points x 64 cout. 8 warps as 4(M) x 2(N); warp tile 32x32.
// A fill: 16 lanes cover one 64-float row (lane quarter = float4), 2 rows/instr.
__global__ void __launch_bounds__(256) k_branch_mma(
    const float* __restrict__ feats, const int* __restrict__ idxs,
    const int* __restrict__ seg,
    const float* __restrict__ w1, const float* __restrict__ bias1,
    const float* __restrict__ w2, const float* __restrict__ bias2,
    const float* __restrict__ w3, const float* __restrict__ bias3)
{
    extern __shared__ float sm[];
    float* sA = sm;                         // [128][68]
    float* sB = sm + SA_ELEMS;              // [64][68]   (cout-major, cin inner)
    int*   snbr = (int*)(sm + SA_ELEMS + SB_ELEMS);  // 128*9

    int tid = threadIdx.x;
    int br  = blockIdx.y;
    int p0  = blockIdx.x * 128;
    const float* w    = (br == 0) ? w1 : (br == 1) ? w2 : w3;
    const float* bias = (br == 0) ? bias1 : (br == 1) ? bias2 : bias3;

    // neighbor table
    for (int t = tid; t < 128 * 9; t += 256) {
        int p = t / 9, k = t % 9;
        int gi = p0 + p;
        int b = idxs[3*gi], y = idxs[3*gi+1], x = idxs[3*gi+2];
        int sgi = seg[gi];
        int d = g_dil[br * NINS + sgi];
        int ky = k / 3 - 1, kx = k % 3 - 1;
        int ny = y + ky * d, nx = x + kx * d;
        int nbr = -1;
        if (ny >= 0 && ny < Hn && nx >= 0 && nx < Wn) {
            int n = g_idx_map[(b * Hn + ny) * Wn + nx];
            if (n >= 0 && seg[n] == sgi) nbr = n;
        }
        snbr[t] = nbr;
    }
    __syncthreads();

    int lane = tid & 31, wid = tid >> 5;
    int wm = wid >> 1, wn = wid & 1;
    int gid = lane >> 2, tig = lane & 3;
    int sub = lane >> 4, li = lane & 15;        // A fill: 2 rows/warp/instr
    int fci = tid >> 2, fq = tid & 3;           // B fill

    float acc[2][4][4];
#pragma unroll
    for (int mi = 0; mi < 2; mi++)
#pragma unroll
        for (int ni = 0; ni < 4; ni++)
#pragma unroll
            for (int e = 0; e < 4; e++) acc[mi][ni][e] = 0.f;

    for (int k = 0; k < 9; k++) {
        // ---- A fill: coalesced gather, 2 rows per warp per iteration ----
#pragma unroll
        for (int j = 0; j < 8; j++) {
            int row = wid * 16 + j * 2 + sub;
            int nbr = snbr[row * 9 + k];
            float4 f = make_float4(0.f, 0.f, 0.f, 0.f);
            if (nbr >= 0) f = ((const float4*)(feats + (size_t)nbr * 64))[li];
            f.x = tf32r(f.x); f.y = tf32r(f.y);
            f.z = tf32r(f.z); f.w = tf32r(f.w);
            *(float4*)(sA + row * APAD + li * 4) = f;
        }
        // ---- B fill: transpose w[k] (cin x cout) -> sB[cout][cin] ----
        {
            const float* wk = w + k * 4096 + fci * 64;
#pragma unroll
            for (int j = 0; j < 4; j++) {
                int n0 = fq * 16 + j * 4;
                float4 f = *(const float4*)(wk + n0);
                sB[(n0 + 0) * APAD + fci] = tf32r(f.x);
                sB[(n0 + 1) * APAD + fci] = tf32r(f.y);
                sB[(n0 + 2) * APAD + fci] = tf32r(f.z);
                sB[(n0 + 3) * APAD + fci] = tf32r(f.w);
            }
        }
        __syncthreads();

#pragma unroll
        for (int s = 0; s < 8; s++) {
            float a[2][4], b[4][2];
#pragma unroll
            for (int mi = 0; mi < 2; mi++) {
                const float* ap = sA + (wm * 32 + mi * 16 + gid) * APAD + s * 8 + tig;
                a[mi][0] = ap[0];
                a[mi][1] = ap[8 * APAD];
                a[mi][2] = ap[4];
                a[mi][3] = ap[8 * APAD + 4];
            }
#pragma unroll
            for (int ni = 0; ni < 4; ni++) {
                const float* bp = sB + (wn * 32 + ni * 8 + gid) * APAD + s * 8 + tig;
                b[ni][0] = bp[0];
                b[ni][1] = bp[4];
            }
#pragma unroll
            for (int mi = 0; mi < 2; mi++)
#pragma unroll
                for (int ni = 0; ni < 4; ni++)
                    mma_tf32(acc[mi][ni], a[mi], b[ni]);
        }
        __syncthreads();
    }

    // epilogue: + bias, write g_h
    float* hout = g_h + (size_t)br * Np * 64;
#pragma unroll
    for (int ni = 0; ni < 4; ni++) {
        int col = wn * 32 + ni * 8 + tig * 2;
        float2 bb = *(const float2*)(bias + col);
#pragma unroll
        for (int mi = 0; mi < 2; mi++) {
            int row = p0 + wm * 32 + mi * 16 + gid;
            float2 v0 = make_float2(acc[mi][ni][0] + bb.x, acc[mi][ni][1] + bb.y);
            float2 v1 = make_float2(acc[mi][ni][2] + bb.x, acc[mi][ni][3] + bb.y);
            *(float2*)(hout + (size_t)row * 64 + col) = v0;
            *(float2*)(hout + (size_t)(row + 8) * 64 + col) = v1;
        }
    }
}

// ---------------- segment stats (proven) ----------------
__global__ void k_stats(const int* __restrict__ seg) {
    int br   = blockIdx.y;
    int base = blockIdx.x * 1024;
    int c  = threadIdx.x & 63;
    int rs = threadIdx.x >> 6;
    const float* h = g_h + (size_t)br * Np * 64;
    float s = 0.f, s2 = 0.f;
    int cur = seg[base + rs];
    for (int j = 0; j < 256; j++) {
        int p = base + rs + 4 * j;
        int sg = seg[p];
        if (sg != cur) {
            atomicAdd(&g_sum [(br * NINS + cur) * 64 + c], s);
            atomicAdd(&g_sum2[(br * NINS + cur) * 64 + c], s2);
            s = 0.f; s2 = 0.f; cur = sg;
        }
        float v = h[(size_t)p * 64 + c];
        s += v; s2 += v * v;
    }
    atomicAdd(&g_sum [(br * NINS + cur) * 64 + c], s);
    atomicAdd(&g_sum2[(br * NINS + cur) * 64 + c], s2);
}

__global__ void k_normfin() {
    int i = blockIdx.x * blockDim.x + threadIdx.x;
    if (i < 3 * NINS * 64) {
        int sgl = (i / 64) % NINS;
        float cnt = (float)g_cnt[sgl];
        float mean = g_sum[i] / cnt;
        float var  = g_sum2[i] / cnt - mean * mean;
        g_mean[i] = mean;
        g_rinv[i] = rsqrtf(var + EPSF);
    }
}

// ---------------- final conv via mma.sync tf32, coalesced gather ----------
__global__ void __launch_bounds__(256) k_final_mma(
    const float* __restrict__ feats, const int* __restrict__ idxs,
    const int* __restrict__ seg, const float* __restrict__ wf,
    const float* __restrict__ bf, float* __restrict__ out)
{
    extern __shared__ float sm[];
    float* sA = sm;
    float* sB = sm + SA_ELEMS;
    int*   snbr  = (int*)(sm + SA_ELEMS + SB_ELEMS);
    int*   snseg = snbr + 128 * 9;

    int tid = threadIdx.x;
    int p0  = blockIdx.x * 128;

    for (int t = tid; t < 128 * 9; t += 256) {
        int p = t / 9, k = t % 9;
        int gi = p0 + p;
        int b = idxs[3*gi], y = idxs[3*gi+1], x = idxs[3*gi+2];
        int ky = k / 3 - 1, kx = k % 3 - 1;
        int ny = y + ky, nx = x + kx;
        int nbr = -1, sgn = 0;
        if (ny >= 0 && ny < Hn && nx >= 0 && nx < Wn) {
            int n = g_idx_map[(b * Hn + ny) * Wn + nx];
            if (n >= 0) { nbr = n; sgn = seg[n]; }
        }
        snbr[t] = nbr; snseg[t] = sgn;
    }
    __syncthreads();

    int lane = tid & 31, wid = tid >> 5;
    int wm = wid >> 1, wn = wid & 1;
    int gid = lane >> 2, tig = lane & 3;
    int sub = lane >> 4, li = lane & 15;
    int fci = tid >> 2, fq = tid & 3;

    float acc[2][4][4];
#pragma unroll
    for (int mi = 0; mi < 2; mi++)
#pragma unroll
        for (int ni = 0; ni < 4; ni++)
#pragma unroll
            for (int e = 0; e < 4; e++) acc[mi][ni][e] = 0.f;

    for (int u = 0; u < 36; u++) {
        int k = u >> 2, c = u & 3;

        // ---- A fill: coalesced, 2 rows per warp per iteration ----
        if (c == 0) {
#pragma unroll
            for (int j = 0; j < 8; j++) {
                int row = wid * 16 + j * 2 + sub;
                int nbr = snbr[row * 9 + k];
                float4 f = make_float4(0.f, 0.f, 0.f, 0.f);
                if (nbr >= 0) f = ((const float4*)(feats + (size_t)nbr * 64))[li];
                f.x = tf32r(f.x); f.y = tf32r(f.y);
                f.z = tf32r(f.z); f.w = tf32r(f.w);
                *(float4*)(sA + row * APAD + li * 4) = f;
            }
        } else {
            int brr = c - 1;
            const float* hbase = g_h + (size_t)brr * Np * 64;
#pragma unroll
            for (int j = 0; j < 8; j++) {
                int row = wid * 16 + j * 2 + sub;
                int nbr = snbr[row * 9 + k];
                float4 v = make_float4(0.f, 0.f, 0.f, 0.f);
                if (nbr >= 0) {
                    float4 hv = ((const float4*)(hbase + (size_t)nbr * 64))[li];
                    int tb = ((brr * NINS + snseg[row * 9 + k]) << 6) + li * 4;
                    float4 mm = *(const float4*)(g_mean + tb);
                    float4 rr = *(const float4*)(g_rinv + tb);
                    v.x = fmaxf(0.f, (hv.x - mm.x) * rr.x);
                    v.y = fmaxf(0.f, (hv.y - mm.y) * rr.y);
                    v.z = fmaxf(0.f, (hv.z - mm.z) * rr.z);
                    v.w = fmaxf(0.f, (hv.w - mm.w) * rr.w);
                }
                v.x = tf32r(v.x); v.y = tf32r(v.y);
                v.z = tf32r(v.z); v.w = tf32r(v.w);
                *(float4*)(sA + row * APAD + li * 4) = v;
            }
        }
        // ---- B fill: wf[k][c*64 + ci][n] -> sB[n][ci] ----
        {
            const float* wk = wf + ((size_t)k * 256 + c * 64 + fci) * 64;
#pragma unroll
            for (int j = 0; j < 4; j++) {
                int n0 = fq * 16 + j * 4;
                float4 f = *(const float4*)(wk + n0);
                sB[(n0 + 0) * APAD + fci] = tf32r(f.x);
                sB[(n0 + 1) * APAD + fci] = tf32r(f.y);
                sB[(n0 + 2) * APAD + fci] = tf32r(f.z);
                sB[(n0 + 3) * APAD + fci] = tf32r(f.w);
            }
        }
        __syncthreads();

#pragma unroll
        for (int s = 0; s < 8; s++) {
            float a[2][4], b[4][2];
#pragma unroll
            for (int mi = 0; mi < 2; mi++) {
                const float* ap = sA + (wm * 32 + mi * 16 + gid) * APAD + s * 8 + tig;
                a[mi][0] = ap[0];
                a[mi][1] = ap[8 * APAD];
                a[mi][2] = ap[4];
                a[mi][3] = ap[8 * APAD + 4];
            }
#pragma unroll
            for (int ni = 0; ni < 4; ni++) {
                const float* bp = sB + (wn * 32 + ni * 8 + gid) * APAD + s * 8 + tig;
                b[ni][0] = bp[0];
                b[ni][1] = bp[4];
            }
#pragma unroll
            for (int mi = 0; mi < 2; mi++)
#pragma unroll
                for (int ni = 0; ni < 4; ni++)
                    mma_tf32(acc[mi][ni], a[mi], b[ni]);
        }
        __syncthreads();
    }

#pragma unroll
    for (int ni = 0; ni < 4; ni++) {
        int col = wn * 32 + ni * 8 + tig * 2;
        float2 bb = *(const float2*)(bf + col);
#pragma unroll
        for (int mi = 0; mi < 2; mi++) {
            int row = p0 + wm * 32 + mi * 16 + gid;
            float2 v0 = make_float2(acc[mi][ni][0] + bb.x, acc[mi][ni][1] + bb.y);
            float2 v1 = make_float2(acc[mi][ni][2] + bb.x, acc[mi][ni][3] + bb.y);
            *(float2*)(out + (size_t)row * 64 + col) = v0;
            *(float2*)(out + (size_t)(row + 8) * 64 + col) = v1;
        }
    }
}

// ---------------- launch ----------------
#define SMEM_BRANCH ((SA_ELEMS + SB_ELEMS + 128 * 9) * 4)
#define SMEM_FINAL  ((SA_ELEMS + SB_ELEMS + 2 * 128 * 9) * 4)

extern "C" void kernel_launch(void* const* d_in, const int* in_sizes, int n_in,
                              void* d_out, int out_size)
{
    const float* feats = (const float*)d_in[0];
    const int*   idxs  = (const int*)  d_in[1];
    const int*   seg   = (const int*)  d_in[2];
    const float* w1    = (const float*)d_in[3];
    const float* b1    = (const float*)d_in[4];
    const float* w2    = (const float*)d_in[5];
    const float* b2    = (const float*)d_in[6];
    const float* w3    = (const float*)d_in[7];
    const float* b3    = (const float*)d_in[8];
    const float* wf    = (const float*)d_in[9];
    const float* bf    = (const float*)d_in[10];
    float* out = (float*)d_out;

    cudaFuncSetAttribute(k_branch_mma, cudaFuncAttributeMaxDynamicSharedMemorySize, SMEM_BRANCH);
    cudaFuncSetAttribute(k_final_mma,  cudaFuncAttributeMaxDynamicSharedMemorySize, SMEM_FINAL);

    k_init<<<(Bn * Hn * Wn + 255) / 256, 256>>>();
    k_scatter<<<(Np + 255) / 256, 256>>>(idxs, seg);
    k_dil<<<1, 64>>>();

    dim3 gb(Np / 128, 3);
    k_branch_mma<<<gb, 256, SMEM_BRANCH>>>(feats, idxs, seg, w1, b1, w2, b2, w3, b3);

    dim3 sg(Np / 1024, 3);
    k_stats<<<sg, 256>>>(seg);
    k_normfin<<<12, 256>>>();

    k_final_mma<<<Np / 128, 256, SMEM_FINAL>>>(feats, idxs, seg, wf, bf, out);
}